// round 1
// baseline (speedup 1.0000x reference)
#include <cuda_runtime.h>
#include <math.h>

#define B_ 2
#define T_ 2048
#define D_ 1024
#define H_ 16
#define HD 64
#define P_ 256
#define NPASS_ 3
#define BT (B_ * T_)          // 4096

// ---------------- scratch (device globals; allocation-free) ----------------
__device__ float g_h[BT * D_];            // rmsnorm1 output
__device__ float g_qkv[BT * 3 * D_];      // qkv projections
__device__ float g_attno[BT * D_];        // attention output (pre O-proj)
__device__ float g_x2[BT * D_];           // x + attn@o_w^T
__device__ float g_h2[BT * D_];           // rmsnorm2 output

// ---------------- rmsnorm (+ gamma/beta) ----------------
__global__ __launch_bounds__(256)
void rmsnorm_kernel(const float* __restrict__ x, const float* __restrict__ w,
                    const float* __restrict__ gamma, const float* __restrict__ beta,
                    float* __restrict__ out) {
    const int row = blockIdx.x;
    const int tid = threadIdx.x;
    const float* xr = x + (size_t)row * D_;
    float v[4];
    float ss = 0.f;
#pragma unroll
    for (int i = 0; i < 4; i++) {
        v[i] = xr[tid + i * 256];
        ss += v[i] * v[i];
    }
    __shared__ float red[8];
#pragma unroll
    for (int o = 16; o > 0; o >>= 1) ss += __shfl_xor_sync(0xffffffffu, ss, o);
    if ((tid & 31) == 0) red[tid >> 5] = ss;
    __syncthreads();
    if (tid < 8) {
        float s = red[tid];
#pragma unroll
        for (int o = 4; o > 0; o >>= 1) s += __shfl_xor_sync(0xffu, s, o);
        if (tid == 0) red[0] = s;
    }
    __syncthreads();
    const float rs = rsqrtf(red[0] * (1.0f / D_) + 1.1920929e-07f);
    float* op = out + (size_t)row * D_;
#pragma unroll
    for (int i = 0; i < 4; i++) {
        const int d = tid + i * 256;
        op[d] = v[i] * rs * w[d] * gamma[d] + beta[d];
    }
}

// ---------------- NT SGEMM: C[M,N] = A[M,K] @ B[N,K]^T (+ optional X) -------
// 128x128 block tile, 8 k-slice, 256 threads, 8x8 per thread.
__global__ __launch_bounds__(256, 2)
void gemm_nt_kernel(const float* __restrict__ A, const float* __restrict__ Bm,
                    const float* __restrict__ X, float* __restrict__ C,
                    int N, int K) {
    __shared__ float As[8][128];
    __shared__ float Bs[8][128];
    const int m0 = blockIdx.y * 128;
    const int n0 = blockIdx.x * 128;
    const int tid = threadIdx.x;
    const int tx = tid & 15;
    const int ty = tid >> 4;
    const int lr = tid >> 1;        // 0..127
    const int lc = (tid & 1) * 4;   // 0 or 4
    const float* Ap = A + (size_t)(m0 + lr) * K + lc;
    const float* Bp = Bm + (size_t)(n0 + lr) * K + lc;

    float acc[8][8];
#pragma unroll
    for (int i = 0; i < 8; i++)
#pragma unroll
        for (int j = 0; j < 8; j++) acc[i][j] = 0.f;

    for (int k0 = 0; k0 < K; k0 += 8) {
        const float4 av = *(const float4*)(Ap + k0);
        const float4 bv = *(const float4*)(Bp + k0);
        __syncthreads();
        As[lc + 0][lr] = av.x; As[lc + 1][lr] = av.y;
        As[lc + 2][lr] = av.z; As[lc + 3][lr] = av.w;
        Bs[lc + 0][lr] = bv.x; Bs[lc + 1][lr] = bv.y;
        Bs[lc + 2][lr] = bv.z; Bs[lc + 3][lr] = bv.w;
        __syncthreads();
#pragma unroll
        for (int kk = 0; kk < 8; kk++) {
            float a[8], b[8];
            *(float4*)&a[0] = *(const float4*)&As[kk][ty * 8];
            *(float4*)&a[4] = *(const float4*)&As[kk][ty * 8 + 4];
            *(float4*)&b[0] = *(const float4*)&Bs[kk][tx * 8];
            *(float4*)&b[4] = *(const float4*)&Bs[kk][tx * 8 + 4];
#pragma unroll
            for (int i = 0; i < 8; i++)
#pragma unroll
                for (int j = 0; j < 8; j++) acc[i][j] += a[i] * b[j];
        }
    }

#pragma unroll
    for (int i = 0; i < 8; i++) {
        const int m = m0 + ty * 8 + i;
#pragma unroll
        for (int j = 0; j < 8; j += 4) {
            const int n = n0 + tx * 8 + j;
            float4 v;
            v.x = acc[i][j]; v.y = acc[i][j + 1]; v.z = acc[i][j + 2]; v.w = acc[i][j + 3];
            if (X) {
                const float4 xv = *(const float4*)(X + (size_t)m * N + n);
                v.x += xv.x; v.y += xv.y; v.z += xv.z; v.w += xv.w;
            }
            *(float4*)(C + (size_t)m * N + n) = v;
        }
    }
}

// ---------------- causal flash attention (fp32) ----------------
// Block: one (b,h,q-tile of 64). 256 threads (16x16). K-tile = 32.
__global__ __launch_bounds__(256)
void attn_kernel(const float* __restrict__ qkv, float* __restrict__ O) {
    __shared__ float Qs[64][65];
    __shared__ float Ks[32][65];
    __shared__ float Vs[32][64];
    __shared__ float Ps[64][33];
    const int q0 = blockIdx.x * 64;
    const int b = blockIdx.y >> 4;
    const int h = blockIdx.y & 15;
    const int tid = threadIdx.x;
    const int tx = tid & 15;
    const int ty = tid >> 4;
    const float* base = qkv + (size_t)b * T_ * 3 * D_ + h * HD;

    // load Q tile
    for (int idx = tid; idx < 64 * 16; idx += 256) {
        const int r = idx >> 4;
        const int c = (idx & 15) * 4;
        const float4 v = *(const float4*)(base + (size_t)(q0 + r) * (3 * D_) + c);
        Qs[r][c] = v.x; Qs[r][c + 1] = v.y; Qs[r][c + 2] = v.z; Qs[r][c + 3] = v.w;
    }
    float m_i[4], l_i[4], acc[4][4];
#pragma unroll
    for (int i = 0; i < 4; i++) {
        m_i[i] = -1e30f; l_i[i] = 0.f;
#pragma unroll
        for (int j = 0; j < 4; j++) acc[i][j] = 0.f;
    }
    __syncthreads();

    for (int k0 = 0; k0 <= q0 + 32; k0 += 32) {
        // load K,V tiles
        for (int idx = tid; idx < 32 * 16; idx += 256) {
            const int r = idx >> 4;
            const int c = (idx & 15) * 4;
            const float* kp = base + (size_t)(k0 + r) * (3 * D_) + D_ + c;
            const float4 kv = *(const float4*)kp;
            Ks[r][c] = kv.x; Ks[r][c + 1] = kv.y; Ks[r][c + 2] = kv.z; Ks[r][c + 3] = kv.w;
            *(float4*)&Vs[r][c] = *(const float4*)(kp + D_);
        }
        __syncthreads();

        // S = Q K^T : 4 rows x 2 cols per thread
        float s[4][2];
#pragma unroll
        for (int i = 0; i < 4; i++) { s[i][0] = 0.f; s[i][1] = 0.f; }
#pragma unroll 4
        for (int d = 0; d < 64; d++) {
            const float b0 = Ks[tx * 2 + 0][d];
            const float b1 = Ks[tx * 2 + 1][d];
#pragma unroll
            for (int i = 0; i < 4; i++) {
                const float a = Qs[ty * 4 + i][d];
                s[i][0] += a * b0;
                s[i][1] += a * b1;
            }
        }
        // scale + causal mask, row max
        float mt[4];
#pragma unroll
        for (int i = 0; i < 4; i++) {
            const int qrow = q0 + ty * 4 + i;
#pragma unroll
            for (int j = 0; j < 2; j++) {
                const int kcol = k0 + tx * 2 + j;
                s[i][j] = (kcol <= qrow) ? s[i][j] * 0.125f : -1e30f;
            }
            mt[i] = fmaxf(s[i][0], s[i][1]);
#pragma unroll
            for (int o = 8; o > 0; o >>= 1)
                mt[i] = fmaxf(mt[i], __shfl_xor_sync(0xffffffffu, mt[i], o, 16));
        }
        float alpha[4], pl[4];
#pragma unroll
        for (int i = 0; i < 4; i++) {
            const float mn = fmaxf(m_i[i], mt[i]);
            alpha[i] = __expf(m_i[i] - mn);
            m_i[i] = mn;
            const float p0 = __expf(s[i][0] - mn);
            const float p1 = __expf(s[i][1] - mn);
            Ps[ty * 4 + i][tx * 2 + 0] = p0;
            Ps[ty * 4 + i][tx * 2 + 1] = p1;
            pl[i] = p0 + p1;
#pragma unroll
            for (int o = 8; o > 0; o >>= 1)
                pl[i] += __shfl_xor_sync(0xffffffffu, pl[i], o, 16);
            l_i[i] = l_i[i] * alpha[i] + pl[i];
#pragma unroll
            for (int j = 0; j < 4; j++) acc[i][j] *= alpha[i];
        }
        __syncthreads();

        // O += P @ V : 4 rows x 4 cols per thread
#pragma unroll 8
        for (int kk = 0; kk < 32; kk++) {
            float bb[4];
            *(float4*)bb = *(const float4*)&Vs[kk][tx * 4];
#pragma unroll
            for (int i = 0; i < 4; i++) {
                const float a = Ps[ty * 4 + i][kk];
#pragma unroll
                for (int j = 0; j < 4; j++) acc[i][j] += a * bb[j];
            }
        }
        __syncthreads();
    }

#pragma unroll
    for (int i = 0; i < 4; i++) {
        const float inv = 1.f / l_i[i];
        const int t = q0 + ty * 4 + i;
        float4 v;
        v.x = acc[i][0] * inv; v.y = acc[i][1] * inv;
        v.z = acc[i][2] * inv; v.w = acc[i][3] * inv;
        *(float4*)(O + (size_t)(b * T_ + t) * D_ + h * HD + tx * 4) = v;
    }
}

// ---------------- rotation passes + silu + final combine ----------------
__global__ __launch_bounds__(256)
void rot_kernel(const float* __restrict__ h2, const float* __restrict__ x2,
                const float* __restrict__ angles, const float* __restrict__ gate,
                const float* __restrict__ bias, const int* __restrict__ pi,
                const int* __restrict__ pj, float* __restrict__ out) {
    const int row = blockIdx.x;
    const int tid = threadIdx.x;
    __shared__ float r[D_];
    const float* hrow = h2 + (size_t)row * D_;
#pragma unroll
    for (int i = 0; i < 4; i++) r[tid + i * 256] = hrow[tid + i * 256];
    __syncthreads();
#pragma unroll
    for (int p = 0; p < NPASS_; p++) {
        const int ii = pi[p * P_ + tid];
        const int jj = pj[p * P_ + tid];
        float sa, ca;
        sincosf(angles[p * P_ + tid], &sa, &ca);
        const float hi = r[ii];
        const float hj = r[jj];
        // pi/pj entries are disjoint within a pass: each location is touched
        // by exactly one thread, so no cross-thread hazard here.
        r[ii] = hi * ca - hj * sa;
        r[jj] = hi * sa + hj * ca;
        __syncthreads();
#pragma unroll
        for (int i = 0; i < 4; i++) {
            const int d = tid + i * 256;
            const float z = r[d] * gate[p * D_ + d] + bias[p * D_ + d];
            r[d] = z / (1.f + __expf(-z));
        }
        __syncthreads();
    }
    const float* xrow = x2 + (size_t)row * D_;
    float* orow = out + (size_t)row * D_;
#pragma unroll
    for (int i = 0; i < 4; i++) {
        const int d = tid + i * 256;
        orow[d] = xrow[d] + r[d] - hrow[d];
    }
}

// ---------------- launch ----------------
extern "C" void kernel_launch(void* const* d_in, const int* in_sizes, int n_in,
                              void* d_out, int out_size) {
    const float* x     = (const float*)d_in[0];
    const float* gamma = (const float*)d_in[1];
    const float* beta  = (const float*)d_in[2];
    const float* qkv_w = (const float*)d_in[3];
    const float* o_w   = (const float*)d_in[4];
    const float* n1w   = (const float*)d_in[5];
    const float* n2w   = (const float*)d_in[6];
    const float* angles= (const float*)d_in[7];
    const float* gate  = (const float*)d_in[8];
    const float* bias  = (const float*)d_in[9];
    const int*   pi    = (const int*)d_in[10];
    const int*   pj    = (const int*)d_in[11];
    float* out = (float*)d_out;

    void *ph, *pqkv, *pattno, *px2, *ph2;
    cudaGetSymbolAddress(&ph, g_h);
    cudaGetSymbolAddress(&pqkv, g_qkv);
    cudaGetSymbolAddress(&pattno, g_attno);
    cudaGetSymbolAddress(&px2, g_x2);
    cudaGetSymbolAddress(&ph2, g_h2);
    float* h = (float*)ph;
    float* qkv = (float*)pqkv;
    float* attno = (float*)pattno;
    float* x2 = (float*)px2;
    float* h2 = (float*)ph2;

    // 1. h = rmsnorm(x, norm1_w) * gamma + beta
    rmsnorm_kernel<<<BT, 256>>>(x, n1w, gamma, beta, h);

    // 2. qkv = h @ qkv_w^T    [4096 x 3072]
    gemm_nt_kernel<<<dim3(3 * D_ / 128, BT / 128), 256>>>(h, qkv_w, nullptr, qkv,
                                                          3 * D_, D_);

    // 3. causal attention -> attno
    attn_kernel<<<dim3(T_ / 64, B_ * H_), 256>>>(qkv, attno);

    // 4. x2 = x + attno @ o_w^T   [4096 x 1024]
    gemm_nt_kernel<<<dim3(D_ / 128, BT / 128), 256>>>(attno, o_w, x, x2, D_, D_);

    // 5. h2 = rmsnorm(x2, norm2_w) * gamma + beta
    rmsnorm_kernel<<<BT, 256>>>(x2, n2w, gamma, beta, h2);

    // 6. rotation passes + silu; out = x2 + r - h2
    rot_kernel<<<BT, 256>>>(h2, x2, angles, gate, bias, pi, pj, out);
}

// round 3
// speedup vs baseline: 4.8245x; 4.8245x over previous
#include <cuda_runtime.h>
#include <cuda_fp16.h>
#include <cstdint>
#include <math.h>

#define B_ 2
#define T_ 2048
#define D_ 1024
#define H_ 16
#define HD 64
#define P_ 256
#define NPASS_ 3
#define BT (B_ * T_)          // 4096

// ---------------- scratch (device globals; allocation-free) ----------------
__device__ __align__(16) half g_h16[BT * D_];          // rmsnorm1 out (fp16)
__device__ __align__(16) half g_w16[4 * D_ * D_];      // qkv_w (3DD) then o_w (DD), fp16
__device__ __align__(16) half g_qkv16[BT * 3 * D_];    // qkv projections fp16
__device__ __align__(16) half g_att16[BT * D_];        // attention out fp16
__device__ __align__(16) float g_x2[BT * D_];          // x + attn@o_w^T
__device__ __align__(16) float g_h2[BT * D_];          // rmsnorm2 out

// ---------------- mma / ldmatrix helpers ----------------
__device__ __forceinline__ uint32_t smem_u32(const void* p) {
    return (uint32_t)__cvta_generic_to_shared(p);
}
__device__ __forceinline__ void ldm_x4(uint32_t& r0, uint32_t& r1, uint32_t& r2,
                                       uint32_t& r3, uint32_t addr) {
    asm volatile("ldmatrix.sync.aligned.m8n8.x4.shared.b16 {%0,%1,%2,%3},[%4];"
                 : "=r"(r0), "=r"(r1), "=r"(r2), "=r"(r3) : "r"(addr));
}
__device__ __forceinline__ void ldm_x4_t(uint32_t& r0, uint32_t& r1, uint32_t& r2,
                                         uint32_t& r3, uint32_t addr) {
    asm volatile("ldmatrix.sync.aligned.m8n8.x4.trans.shared.b16 {%0,%1,%2,%3},[%4];"
                 : "=r"(r0), "=r"(r1), "=r"(r2), "=r"(r3) : "r"(addr));
}
__device__ __forceinline__ void mma16816(float* c, const uint32_t* a, const uint32_t* b) {
    asm volatile(
        "mma.sync.aligned.m16n8k16.row.col.f32.f16.f16.f32 "
        "{%0,%1,%2,%3},{%4,%5,%6,%7},{%8,%9},{%0,%1,%2,%3};"
        : "+f"(c[0]), "+f"(c[1]), "+f"(c[2]), "+f"(c[3])
        : "r"(a[0]), "r"(a[1]), "r"(a[2]), "r"(a[3]), "r"(b[0]), "r"(b[1]));
}
// pack two floats into one u32 holding a half2 (bit cast; no such intrinsic exists)
__device__ __forceinline__ uint32_t h2u(float a, float b) {
    half2 h = __floats2half2_rn(a, b);
    uint32_t u;
    asm volatile("mov.b32 %0, %1;" : "=r"(u) : "r"(*reinterpret_cast<uint32_t*>(&h)));
    return u;
}

// ---------------- f32 -> f16 conversion (weights) ----------------
__global__ __launch_bounds__(256)
void f2h4_kernel(const float* __restrict__ in, half* __restrict__ out, int n4) {
    int i = blockIdx.x * 256 + threadIdx.x;
    if (i < n4) {
        float4 v = ((const float4*)in)[i];
        half2* o = (half2*)out + i * 2;
        o[0] = __floats2half2_rn(v.x, v.y);
        o[1] = __floats2half2_rn(v.z, v.w);
    }
}

// ---------------- rmsnorm (+ gamma/beta), fp32 in, T out ----------------
template <typename T>
__global__ __launch_bounds__(256)
void rmsnorm_kernel(const float* __restrict__ x, const float* __restrict__ w,
                    const float* __restrict__ gamma, const float* __restrict__ beta,
                    T* __restrict__ out) {
    const int row = blockIdx.x;
    const int tid = threadIdx.x;
    const float* xr = x + (size_t)row * D_;
    float v[4];
    float ss = 0.f;
#pragma unroll
    for (int i = 0; i < 4; i++) {
        v[i] = xr[tid + i * 256];
        ss += v[i] * v[i];
    }
    __shared__ float red[8];
#pragma unroll
    for (int o = 16; o > 0; o >>= 1) ss += __shfl_xor_sync(0xffffffffu, ss, o);
    if ((tid & 31) == 0) red[tid >> 5] = ss;
    __syncthreads();
    if (tid < 8) {
        float s = red[tid];
#pragma unroll
        for (int o = 4; o > 0; o >>= 1) s += __shfl_xor_sync(0xffu, s, o);
        if (tid == 0) red[0] = s;
    }
    __syncthreads();
    const float rs = rsqrtf(red[0] * (1.0f / D_) + 1.1920929e-07f);
    T* op = out + (size_t)row * D_;
#pragma unroll
    for (int i = 0; i < 4; i++) {
        const int d = tid + i * 256;
        op[d] = (T)(v[i] * rs * w[d] * gamma[d] + beta[d]);
    }
}

// ---------------- fp16 NT GEMM: C[M,N] = A[M,K] @ B[N,K]^T ----------------
// CTA 128x128, k-chunk 32, 8 warps (2m x 4n), warp tile 64x32, HMMA 16x8x16.
#define SA 40
template <bool HALF_OUT, bool ADD_X>
__global__ __launch_bounds__(256, 1)
void gemm16_kernel(const half* __restrict__ A, const half* __restrict__ Bw,
                   const float* __restrict__ X, void* __restrict__ Cout,
                   int M, int N, int K) {
    __shared__ __align__(16) half As[2][128][SA];
    __shared__ __align__(16) half Bs[2][128][SA];
    const int tid = threadIdx.x, lane = tid & 31, w = tid >> 5;
    const int m0 = blockIdx.y * 128, n0 = blockIdx.x * 128;
    const int wm = (w >> 2) * 64, wn = (w & 3) * 32;
    const int lr = tid >> 1, lc = (tid & 1) * 16;
    const half* Ag = A + (size_t)(m0 + lr) * K + lc;
    const half* Bg = Bw + (size_t)(n0 + lr) * K + lc;

    float acc[4][4][4];
#pragma unroll
    for (int i = 0; i < 4; i++) {
#pragma unroll
        for (int j = 0; j < 4; j++) {
#pragma unroll
            for (int e = 0; e < 4; e++) acc[i][j][e] = 0.f;
        }
    }

    // preload tile 0
    uint4 pa0 = *(const uint4*)(Ag);
    uint4 pa1 = *(const uint4*)(Ag + 8);
    uint4 pb0 = *(const uint4*)(Bg);
    uint4 pb1 = *(const uint4*)(Bg + 8);
    *(uint4*)&As[0][lr][lc] = pa0;
    *(uint4*)&As[0][lr][lc + 8] = pa1;
    *(uint4*)&Bs[0][lr][lc] = pb0;
    *(uint4*)&Bs[0][lr][lc + 8] = pb1;
    __syncthreads();

    const int kt = K >> 5;
    for (int t = 0; t < kt; t++) {
        const int cur = t & 1;
        if (t + 1 < kt) {
            const half* Ap = Ag + (t + 1) * 32;
            const half* Bp = Bg + (t + 1) * 32;
            pa0 = *(const uint4*)(Ap);
            pa1 = *(const uint4*)(Ap + 8);
            pb0 = *(const uint4*)(Bp);
            pb1 = *(const uint4*)(Bp + 8);
        }
#pragma unroll
        for (int kk = 0; kk < 32; kk += 16) {
            uint32_t af[4][4];
            uint32_t bf[4][2];
#pragma unroll
            for (int mf = 0; mf < 4; mf++) {
                const int row = wm + mf * 16 + (lane & 15);
                const int col = kk + ((lane >> 4) << 3);
                ldm_x4(af[mf][0], af[mf][1], af[mf][2], af[mf][3],
                       smem_u32(&As[cur][row][col]));
            }
#pragma unroll
            for (int nf4 = 0; nf4 < 2; nf4++) {
                const int row = wn + nf4 * 16 + ((lane >> 4) << 3) + (lane & 7);
                const int col = kk + (((lane >> 3) & 1) << 3);
                uint32_t r0, r1, r2, r3;
                ldm_x4(r0, r1, r2, r3, smem_u32(&Bs[cur][row][col]));
                bf[nf4 * 2][0] = r0;
                bf[nf4 * 2][1] = r1;
                bf[nf4 * 2 + 1][0] = r2;
                bf[nf4 * 2 + 1][1] = r3;
            }
#pragma unroll
            for (int mf = 0; mf < 4; mf++) {
#pragma unroll
                for (int nf = 0; nf < 4; nf++) mma16816(acc[mf][nf], af[mf], bf[nf]);
            }
        }
        if (t + 1 < kt) {
            const int nxt = cur ^ 1;
            *(uint4*)&As[nxt][lr][lc] = pa0;
            *(uint4*)&As[nxt][lr][lc + 8] = pa1;
            *(uint4*)&Bs[nxt][lr][lc] = pb0;
            *(uint4*)&Bs[nxt][lr][lc + 8] = pb1;
        }
        __syncthreads();
    }

    const int r_lo = lane >> 2;
    const int c_off = (lane & 3) * 2;
#pragma unroll
    for (int mf = 0; mf < 4; mf++) {
        const int gr0 = m0 + wm + mf * 16 + r_lo;
        const int gr1 = gr0 + 8;
#pragma unroll
        for (int nf = 0; nf < 4; nf++) {
            const int gc = n0 + wn + nf * 8 + c_off;
            if constexpr (HALF_OUT) {
                half* C = (half*)Cout;
                *(half2*)(C + (size_t)gr0 * N + gc) =
                    __floats2half2_rn(acc[mf][nf][0], acc[mf][nf][1]);
                *(half2*)(C + (size_t)gr1 * N + gc) =
                    __floats2half2_rn(acc[mf][nf][2], acc[mf][nf][3]);
            } else {
                float* C = (float*)Cout;
                float v0 = acc[mf][nf][0];
                float v1 = acc[mf][nf][1];
                float v2 = acc[mf][nf][2];
                float v3 = acc[mf][nf][3];
                if constexpr (ADD_X) {
                    float2 x0 = *(const float2*)(X + (size_t)gr0 * N + gc);
                    float2 x1 = *(const float2*)(X + (size_t)gr1 * N + gc);
                    v0 += x0.x; v1 += x0.y; v2 += x1.x; v3 += x1.y;
                }
                *(float2*)(C + (size_t)gr0 * N + gc) = make_float2(v0, v1);
                *(float2*)(C + (size_t)gr1 * N + gc) = make_float2(v2, v3);
            }
        }
    }
}

// ---------------- fp16 causal flash attention ----------------
// CTA: 128 q-rows, 8 warps x 16 rows. KV tile 64. hd = 64.
__global__ __launch_bounds__(256, 1)
void attn16_kernel(const half* __restrict__ qkv, half* __restrict__ attno) {
    __shared__ __align__(16) half Qs[128][72];
    __shared__ __align__(16) half Ks[64][72];
    __shared__ __align__(16) half Vs[64][72];
    const int tid = threadIdx.x, lane = tid & 31, w = tid >> 5;
    const int q0 = blockIdx.x * 128;
    const int b = blockIdx.y >> 4, h = blockIdx.y & 15;
    const size_t rstride = 3 * D_;
    const half* qbase = qkv + (size_t)b * T_ * rstride + h * HD;

    // load Q tile [128][64]
#pragma unroll
    for (int i = 0; i < 4; i++) {
        const int v = tid + i * 256;
        const int r = v >> 3;
        const int c = (v & 7) * 8;
        *(uint4*)&Qs[r][c] = *(const uint4*)(qbase + (size_t)(q0 + r) * rstride + c);
    }
    __syncthreads();

    uint32_t qf[4][4];
    const int qrow = w * 16 + (lane & 15);
#pragma unroll
    for (int kk = 0; kk < 4; kk++) {
        const int col = kk * 16 + ((lane >> 4) << 3);
        ldm_x4(qf[kk][0], qf[kk][1], qf[kk][2], qf[kk][3], smem_u32(&Qs[qrow][col]));
    }

    float of[8][4];
#pragma unroll
    for (int nf = 0; nf < 8; nf++) {
#pragma unroll
        for (int e = 0; e < 4; e++) of[nf][e] = 0.f;
    }
    float m0 = -1e30f, m1 = -1e30f, l0 = 0.f, l1 = 0.f;
    const int r_lo = lane >> 2;
    const int c_off = (lane & 3) * 2;
    const int row0 = q0 + w * 16 + r_lo;   // global q row (low); high = row0+8

    for (int k0 = 0; k0 < q0 + 128; k0 += 64) {
        // load K,V tiles [64][64]
#pragma unroll
        for (int i = 0; i < 2; i++) {
            const int v = tid + i * 256;
            const int r = v >> 3;
            const int c = (v & 7) * 8;
            const half* kp = qbase + (size_t)(k0 + r) * rstride + D_ + c;
            *(uint4*)&Ks[r][c] = *(const uint4*)(kp);
            *(uint4*)&Vs[r][c] = *(const uint4*)(kp + D_);
        }
        __syncthreads();

        // S = Q @ K^T
        float sf[8][4];
#pragma unroll
        for (int nf = 0; nf < 8; nf++) {
#pragma unroll
            for (int e = 0; e < 4; e++) sf[nf][e] = 0.f;
        }
#pragma unroll
        for (int kk = 0; kk < 4; kk++) {
            uint32_t kf[8][2];
#pragma unroll
            for (int nf4 = 0; nf4 < 4; nf4++) {
                const int row = nf4 * 16 + ((lane >> 4) << 3) + (lane & 7);
                const int col = kk * 16 + (((lane >> 3) & 1) << 3);
                uint32_t r0, r1, r2, r3;
                ldm_x4(r0, r1, r2, r3, smem_u32(&Ks[row][col]));
                kf[nf4 * 2][0] = r0;
                kf[nf4 * 2][1] = r1;
                kf[nf4 * 2 + 1][0] = r2;
                kf[nf4 * 2 + 1][1] = r3;
            }
#pragma unroll
            for (int nf = 0; nf < 8; nf++) mma16816(sf[nf], qf[kk], kf[nf]);
        }

        // scale + causal mask
        const bool domask = (k0 + 63 > row0);
#pragma unroll
        for (int nf = 0; nf < 8; nf++) {
#pragma unroll
            for (int e = 0; e < 4; e++) sf[nf][e] *= 0.125f;
            if (domask) {
                const int col = k0 + nf * 8 + c_off;
                if (col > row0) sf[nf][0] = -1e30f;
                if (col + 1 > row0) sf[nf][1] = -1e30f;
                if (col > row0 + 8) sf[nf][2] = -1e30f;
                if (col + 1 > row0 + 8) sf[nf][3] = -1e30f;
            }
        }

        // online softmax
        float mt0 = -1e30f, mt1 = -1e30f;
#pragma unroll
        for (int nf = 0; nf < 8; nf++) {
            mt0 = fmaxf(mt0, fmaxf(sf[nf][0], sf[nf][1]));
            mt1 = fmaxf(mt1, fmaxf(sf[nf][2], sf[nf][3]));
        }
        mt0 = fmaxf(mt0, __shfl_xor_sync(0xffffffffu, mt0, 1));
        mt0 = fmaxf(mt0, __shfl_xor_sync(0xffffffffu, mt0, 2));
        mt1 = fmaxf(mt1, __shfl_xor_sync(0xffffffffu, mt1, 1));
        mt1 = fmaxf(mt1, __shfl_xor_sync(0xffffffffu, mt1, 2));
        const float mn0 = fmaxf(m0, mt0);
        const float mn1 = fmaxf(m1, mt1);
        const float al0 = __expf(m0 - mn0);
        const float al1 = __expf(m1 - mn1);
        m0 = mn0;
        m1 = mn1;
        float rs0 = 0.f, rs1 = 0.f;
#pragma unroll
        for (int nf = 0; nf < 8; nf++) {
            sf[nf][0] = __expf(sf[nf][0] - mn0);
            sf[nf][1] = __expf(sf[nf][1] - mn0);
            sf[nf][2] = __expf(sf[nf][2] - mn1);
            sf[nf][3] = __expf(sf[nf][3] - mn1);
            rs0 += sf[nf][0] + sf[nf][1];
            rs1 += sf[nf][2] + sf[nf][3];
        }
        rs0 += __shfl_xor_sync(0xffffffffu, rs0, 1);
        rs0 += __shfl_xor_sync(0xffffffffu, rs0, 2);
        rs1 += __shfl_xor_sync(0xffffffffu, rs1, 1);
        rs1 += __shfl_xor_sync(0xffffffffu, rs1, 2);
        l0 = l0 * al0 + rs0;
        l1 = l1 * al1 + rs1;
#pragma unroll
        for (int nf = 0; nf < 8; nf++) {
            of[nf][0] *= al0;
            of[nf][1] *= al0;
            of[nf][2] *= al1;
            of[nf][3] *= al1;
        }

        // P fragments (A-operand layout)
        uint32_t pf[4][4];
#pragma unroll
        for (int kk = 0; kk < 4; kk++) {
            pf[kk][0] = h2u(sf[2 * kk][0], sf[2 * kk][1]);
            pf[kk][1] = h2u(sf[2 * kk][2], sf[2 * kk][3]);
            pf[kk][2] = h2u(sf[2 * kk + 1][0], sf[2 * kk + 1][1]);
            pf[kk][3] = h2u(sf[2 * kk + 1][2], sf[2 * kk + 1][3]);
        }

        // O += P @ V
#pragma unroll
        for (int kk = 0; kk < 4; kk++) {
            uint32_t vf[8][2];
#pragma unroll
            for (int nf4 = 0; nf4 < 4; nf4++) {
                const int row = kk * 16 + (lane & 15);
                const int col = nf4 * 16 + ((lane >> 4) << 3);
                uint32_t r0, r1, r2, r3;
                ldm_x4_t(r0, r1, r2, r3, smem_u32(&Vs[row][col]));
                vf[nf4 * 2][0] = r0;
                vf[nf4 * 2][1] = r1;
                vf[nf4 * 2 + 1][0] = r2;
                vf[nf4 * 2 + 1][1] = r3;
            }
#pragma unroll
            for (int nf = 0; nf < 8; nf++) mma16816(of[nf], pf[kk], vf[nf]);
        }
        __syncthreads();
    }

    const float inv0 = 1.f / l0;
    const float inv1 = 1.f / l1;
    half* obase = attno + h * HD;
#pragma unroll
    for (int nf = 0; nf < 8; nf++) {
        const int c = nf * 8 + c_off;
        *(half2*)(obase + ((size_t)b * T_ + row0) * D_ + c) =
            __floats2half2_rn(of[nf][0] * inv0, of[nf][1] * inv0);
        *(half2*)(obase + ((size_t)b * T_ + row0 + 8) * D_ + c) =
            __floats2half2_rn(of[nf][2] * inv1, of[nf][3] * inv1);
    }
}

// ---------------- rotation passes + silu + final combine ----------------
__global__ __launch_bounds__(256)
void rot_kernel(const float* __restrict__ h2, const float* __restrict__ x2,
                const float* __restrict__ angles, const float* __restrict__ gate,
                const float* __restrict__ bias, const int* __restrict__ pi,
                const int* __restrict__ pj, float* __restrict__ out) {
    const int row = blockIdx.x;
    const int tid = threadIdx.x;
    __shared__ float r[D_];
    const float* hrow = h2 + (size_t)row * D_;
#pragma unroll
    for (int i = 0; i < 4; i++) r[tid + i * 256] = hrow[tid + i * 256];
    __syncthreads();
#pragma unroll
    for (int p = 0; p < NPASS_; p++) {
        const int ii = pi[p * P_ + tid];
        const int jj = pj[p * P_ + tid];
        float sa, ca;
        sincosf(angles[p * P_ + tid], &sa, &ca);
        const float hi = r[ii];
        const float hj = r[jj];
        r[ii] = hi * ca - hj * sa;     // pi/pj disjoint within a pass
        r[jj] = hi * sa + hj * ca;
        __syncthreads();
#pragma unroll
        for (int i = 0; i < 4; i++) {
            const int d = tid + i * 256;
            const float z = r[d] * gate[p * D_ + d] + bias[p * D_ + d];
            r[d] = z / (1.f + __expf(-z));
        }
        __syncthreads();
    }
    const float* xrow = x2 + (size_t)row * D_;
    float* orow = out + (size_t)row * D_;
#pragma unroll
    for (int i = 0; i < 4; i++) {
        const int d = tid + i * 256;
        orow[d] = xrow[d] + r[d] - hrow[d];
    }
}

// ---------------- launch ----------------
extern "C" void kernel_launch(void* const* d_in, const int* in_sizes, int n_in,
                              void* d_out, int out_size) {
    const float* x      = (const float*)d_in[0];
    const float* gamma  = (const float*)d_in[1];
    const float* beta   = (const float*)d_in[2];
    const float* qkv_w  = (const float*)d_in[3];
    const float* o_w    = (const float*)d_in[4];
    const float* n1w    = (const float*)d_in[5];
    const float* n2w    = (const float*)d_in[6];
    const float* angles = (const float*)d_in[7];
    const float* gate   = (const float*)d_in[8];
    const float* bias   = (const float*)d_in[9];
    const int*   pi     = (const int*)d_in[10];
    const int*   pj     = (const int*)d_in[11];
    float* out = (float*)d_out;

    void *ph16, *pw16, *pqkv16, *patt16, *px2, *ph2;
    cudaGetSymbolAddress(&ph16, g_h16);
    cudaGetSymbolAddress(&pw16, g_w16);
    cudaGetSymbolAddress(&pqkv16, g_qkv16);
    cudaGetSymbolAddress(&patt16, g_att16);
    cudaGetSymbolAddress(&px2, g_x2);
    cudaGetSymbolAddress(&ph2, g_h2);
    half* h16   = (half*)ph16;
    half* w16   = (half*)pw16;       // [0, 3DD): qkv_w ; [3DD, 4DD): o_w
    half* qkv16 = (half*)pqkv16;
    half* att16 = (half*)patt16;
    float* x2   = (float*)px2;
    float* h2   = (float*)ph2;

    // weight conversion
    f2h4_kernel<<<(3 * D_ * D_ / 4 + 255) / 256, 256>>>(qkv_w, w16, 3 * D_ * D_ / 4);
    f2h4_kernel<<<(D_ * D_ / 4 + 255) / 256, 256>>>(o_w, w16 + 3 * D_ * D_, D_ * D_ / 4);

    // 1. h = rmsnorm(x, norm1_w) * gamma + beta  (fp16 out)
    rmsnorm_kernel<half><<<BT, 256>>>(x, n1w, gamma, beta, h16);

    // 2. qkv = h @ qkv_w^T  [4096 x 3072] fp16
    gemm16_kernel<true, false><<<dim3(3 * D_ / 128, BT / 128), 256>>>(
        h16, w16, nullptr, qkv16, BT, 3 * D_, D_);

    // 3. causal flash attention (fp16 tensor cores)
    attn16_kernel<<<dim3(T_ / 128, B_ * H_), 256>>>(qkv16, att16);

    // 4. x2 = x + attn @ o_w^T  [4096 x 1024] fp32
    gemm16_kernel<false, true><<<dim3(D_ / 128, BT / 128), 256>>>(
        att16, w16 + 3 * D_ * D_, x, x2, BT, D_, D_);

    // 5. h2 = rmsnorm(x2, norm2_w) * gamma + beta (fp32)
    rmsnorm_kernel<float><<<BT, 256>>>(x2, n2w, gamma, beta, h2);

    // 6. rotation passes + silu; out = x2 + r - h2
    rot_kernel<<<BT, 256>>>(h2, x2, angles, gate, bias, pi, pj, out);
}

// round 4
// speedup vs baseline: 5.2710x; 1.0926x over previous
#include <cuda_runtime.h>
#include <cuda_fp16.h>
#include <cstdint>
#include <math.h>

#define B_ 2
#define T_ 2048
#define D_ 1024
#define H_ 16
#define HD 64
#define P_ 256
#define NPASS_ 3
#define BT (B_ * T_)          // 4096

// ---------------- scratch (device globals; allocation-free) ----------------
__device__ __align__(16) half g_h16[BT * D_];          // rmsnorm1 out (fp16)
__device__ __align__(16) half g_w16[4 * D_ * D_];      // qkv_w (3DD) then o_w (DD), fp16
__device__ __align__(16) half g_qkv16[BT * 3 * D_];    // qkv projections fp16
__device__ __align__(16) half g_att16[BT * D_];        // attention out fp16
__device__ __align__(16) float g_x2[BT * D_];          // x + attn@o_w^T
__device__ __align__(16) float g_h2[BT * D_];          // rmsnorm2 out

// ---------------- mma / ldmatrix helpers ----------------
__device__ __forceinline__ uint32_t smem_u32(const void* p) {
    return (uint32_t)__cvta_generic_to_shared(p);
}
__device__ __forceinline__ void ldm_x4(uint32_t& r0, uint32_t& r1, uint32_t& r2,
                                       uint32_t& r3, uint32_t addr) {
    asm volatile("ldmatrix.sync.aligned.m8n8.x4.shared.b16 {%0,%1,%2,%3},[%4];"
                 : "=r"(r0), "=r"(r1), "=r"(r2), "=r"(r3) : "r"(addr));
}
__device__ __forceinline__ void ldm_x4_t(uint32_t& r0, uint32_t& r1, uint32_t& r2,
                                         uint32_t& r3, uint32_t addr) {
    asm volatile("ldmatrix.sync.aligned.m8n8.x4.trans.shared.b16 {%0,%1,%2,%3},[%4];"
                 : "=r"(r0), "=r"(r1), "=r"(r2), "=r"(r3) : "r"(addr));
}
__device__ __forceinline__ void mma16816(float* c, const uint32_t* a, const uint32_t* b) {
    asm volatile(
        "mma.sync.aligned.m16n8k16.row.col.f32.f16.f16.f32 "
        "{%0,%1,%2,%3},{%4,%5,%6,%7},{%8,%9},{%0,%1,%2,%3};"
        : "+f"(c[0]), "+f"(c[1]), "+f"(c[2]), "+f"(c[3])
        : "r"(a[0]), "r"(a[1]), "r"(a[2]), "r"(a[3]), "r"(b[0]), "r"(b[1]));
}
// pack two floats into one u32 holding a half2
__device__ __forceinline__ uint32_t h2u(float a, float b) {
    half2 h = __floats2half2_rn(a, b);
    uint32_t u;
    asm volatile("mov.b32 %0, %1;" : "=r"(u) : "r"(*reinterpret_cast<uint32_t*>(&h)));
    return u;
}

// ---------------- f32 -> f16 conversion (weights) ----------------
__global__ __launch_bounds__(256)
void f2h4_kernel(const float* __restrict__ in, half* __restrict__ out, int n4) {
    int i = blockIdx.x * 256 + threadIdx.x;
    if (i < n4) {
        float4 v = ((const float4*)in)[i];
        half2* o = (half2*)out + i * 2;
        o[0] = __floats2half2_rn(v.x, v.y);
        o[1] = __floats2half2_rn(v.z, v.w);
    }
}

// ---------------- rmsnorm (+ gamma/beta), fp32 in, T out ----------------
template <typename T>
__global__ __launch_bounds__(256)
void rmsnorm_kernel(const float* __restrict__ x, const float* __restrict__ w,
                    const float* __restrict__ gamma, const float* __restrict__ beta,
                    T* __restrict__ out) {
    const int row = blockIdx.x;
    const int tid = threadIdx.x;
    const float* xr = x + (size_t)row * D_;
    float v[4];
    float ss = 0.f;
#pragma unroll
    for (int i = 0; i < 4; i++) {
        v[i] = xr[tid + i * 256];
        ss += v[i] * v[i];
    }
    __shared__ float red[8];
#pragma unroll
    for (int o = 16; o > 0; o >>= 1) ss += __shfl_xor_sync(0xffffffffu, ss, o);
    if ((tid & 31) == 0) red[tid >> 5] = ss;
    __syncthreads();
    if (tid < 8) {
        float s = red[tid];
#pragma unroll
        for (int o = 4; o > 0; o >>= 1) s += __shfl_xor_sync(0xffu, s, o);
        if (tid == 0) red[0] = s;
    }
    __syncthreads();
    const float rs = rsqrtf(red[0] * (1.0f / D_) + 1.1920929e-07f);
    T* op = out + (size_t)row * D_;
#pragma unroll
    for (int i = 0; i < 4; i++) {
        const int d = tid + i * 256;
        op[d] = (T)(v[i] * rs * w[d] * gamma[d] + beta[d]);
    }
}

// ---------------- fp16 NT GEMM: C[M,N] = A[M,K] @ B[N,K]^T ----------------
// CTA 128x128, 4 warps (2m x 2n), warp tile 64x64, k-chunk 32, double buffer.
// 2 CTAs/SM: independent barrier domains per SMSP pair for latency hiding.
#define SA 40
template <bool HALF_OUT, bool ADD_X>
__global__ __launch_bounds__(128, 2)
void gemm16_kernel(const half* __restrict__ A, const half* __restrict__ Bw,
                   const float* __restrict__ X, void* __restrict__ Cout,
                   int M, int N, int K) {
    __shared__ __align__(16) half As[2][128][SA];
    __shared__ __align__(16) half Bs[2][128][SA];
    const int tid = threadIdx.x, lane = tid & 31, w = tid >> 5;
    const int m0 = blockIdx.y * 128, n0 = blockIdx.x * 128;
    const int wm = (w >> 1) * 64, wn = (w & 1) * 64;
    const int lr = tid >> 1;          // 0..63
    const int lc = (tid & 1) * 16;    // 0 or 16
    const half* Ag0 = A + (size_t)(m0 + lr) * K + lc;
    const half* Ag1 = A + (size_t)(m0 + lr + 64) * K + lc;
    const half* Bg0 = Bw + (size_t)(n0 + lr) * K + lc;
    const half* Bg1 = Bw + (size_t)(n0 + lr + 64) * K + lc;

    float acc[4][8][4];
#pragma unroll
    for (int i = 0; i < 4; i++) {
#pragma unroll
        for (int j = 0; j < 8; j++) {
#pragma unroll
            for (int e = 0; e < 4; e++) acc[i][j][e] = 0.f;
        }
    }

    // preload tile 0
    uint4 pa0 = *(const uint4*)(Ag0);
    uint4 pa1 = *(const uint4*)(Ag0 + 8);
    uint4 pa2 = *(const uint4*)(Ag1);
    uint4 pa3 = *(const uint4*)(Ag1 + 8);
    uint4 pb0 = *(const uint4*)(Bg0);
    uint4 pb1 = *(const uint4*)(Bg0 + 8);
    uint4 pb2 = *(const uint4*)(Bg1);
    uint4 pb3 = *(const uint4*)(Bg1 + 8);
    *(uint4*)&As[0][lr][lc] = pa0;
    *(uint4*)&As[0][lr][lc + 8] = pa1;
    *(uint4*)&As[0][lr + 64][lc] = pa2;
    *(uint4*)&As[0][lr + 64][lc + 8] = pa3;
    *(uint4*)&Bs[0][lr][lc] = pb0;
    *(uint4*)&Bs[0][lr][lc + 8] = pb1;
    *(uint4*)&Bs[0][lr + 64][lc] = pb2;
    *(uint4*)&Bs[0][lr + 64][lc + 8] = pb3;
    __syncthreads();

    const int kt = K >> 5;
    for (int t = 0; t < kt; t++) {
        const int cur = t & 1;
        if (t + 1 < kt) {
            const int ko = (t + 1) * 32;
            pa0 = *(const uint4*)(Ag0 + ko);
            pa1 = *(const uint4*)(Ag0 + ko + 8);
            pa2 = *(const uint4*)(Ag1 + ko);
            pa3 = *(const uint4*)(Ag1 + ko + 8);
            pb0 = *(const uint4*)(Bg0 + ko);
            pb1 = *(const uint4*)(Bg0 + ko + 8);
            pb2 = *(const uint4*)(Bg1 + ko);
            pb3 = *(const uint4*)(Bg1 + ko + 8);
        }
#pragma unroll
        for (int kk = 0; kk < 32; kk += 16) {
            uint32_t af[4][4];
            uint32_t bf[8][2];
#pragma unroll
            for (int mf = 0; mf < 4; mf++) {
                const int row = wm + mf * 16 + (lane & 15);
                const int col = kk + ((lane >> 4) << 3);
                ldm_x4(af[mf][0], af[mf][1], af[mf][2], af[mf][3],
                       smem_u32(&As[cur][row][col]));
            }
#pragma unroll
            for (int nf4 = 0; nf4 < 4; nf4++) {
                const int row = wn + nf4 * 16 + ((lane >> 4) << 3) + (lane & 7);
                const int col = kk + (((lane >> 3) & 1) << 3);
                uint32_t r0, r1, r2, r3;
                ldm_x4(r0, r1, r2, r3, smem_u32(&Bs[cur][row][col]));
                bf[nf4 * 2][0] = r0;
                bf[nf4 * 2][1] = r1;
                bf[nf4 * 2 + 1][0] = r2;
                bf[nf4 * 2 + 1][1] = r3;
            }
#pragma unroll
            for (int mf = 0; mf < 4; mf++) {
#pragma unroll
                for (int nf = 0; nf < 8; nf++) mma16816(acc[mf][nf], af[mf], bf[nf]);
            }
        }
        if (t + 1 < kt) {
            const int nxt = cur ^ 1;
            *(uint4*)&As[nxt][lr][lc] = pa0;
            *(uint4*)&As[nxt][lr][lc + 8] = pa1;
            *(uint4*)&As[nxt][lr + 64][lc] = pa2;
            *(uint4*)&As[nxt][lr + 64][lc + 8] = pa3;
            *(uint4*)&Bs[nxt][lr][lc] = pb0;
            *(uint4*)&Bs[nxt][lr][lc + 8] = pb1;
            *(uint4*)&Bs[nxt][lr + 64][lc] = pb2;
            *(uint4*)&Bs[nxt][lr + 64][lc + 8] = pb3;
        }
        __syncthreads();
    }

    const int r_lo = lane >> 2;
    const int c_off = (lane & 3) * 2;
#pragma unroll
    for (int mf = 0; mf < 4; mf++) {
        const int gr0 = m0 + wm + mf * 16 + r_lo;
        const int gr1 = gr0 + 8;
#pragma unroll
        for (int nf = 0; nf < 8; nf++) {
            const int gc = n0 + wn + nf * 8 + c_off;
            if constexpr (HALF_OUT) {
                half* C = (half*)Cout;
                *(half2*)(C + (size_t)gr0 * N + gc) =
                    __floats2half2_rn(acc[mf][nf][0], acc[mf][nf][1]);
                *(half2*)(C + (size_t)gr1 * N + gc) =
                    __floats2half2_rn(acc[mf][nf][2], acc[mf][nf][3]);
            } else {
                float* C = (float*)Cout;
                float v0 = acc[mf][nf][0];
                float v1 = acc[mf][nf][1];
                float v2 = acc[mf][nf][2];
                float v3 = acc[mf][nf][3];
                if constexpr (ADD_X) {
                    float2 x0 = *(const float2*)(X + (size_t)gr0 * N + gc);
                    float2 x1 = *(const float2*)(X + (size_t)gr1 * N + gc);
                    v0 += x0.x; v1 += x0.y; v2 += x1.x; v3 += x1.y;
                }
                *(float2*)(C + (size_t)gr0 * N + gc) = make_float2(v0, v1);
                *(float2*)(C + (size_t)gr1 * N + gc) = make_float2(v2, v3);
            }
        }
    }
}

// ---------------- fp16 causal flash attention ----------------
// CTA: 128 q-rows, 8 warps x 16 rows. KV tile 64. hd = 64.
__global__ __launch_bounds__(256, 1)
void attn16_kernel(const half* __restrict__ qkv, half* __restrict__ attno) {
    __shared__ __align__(16) half Qs[128][72];
    __shared__ __align__(16) half Ks[64][72];
    __shared__ __align__(16) half Vs[64][72];
    const int tid = threadIdx.x, lane = tid & 31, w = tid >> 5;
    const int q0 = blockIdx.x * 128;
    const int b = blockIdx.y >> 4, h = blockIdx.y & 15;
    const size_t rstride = 3 * D_;
    const half* qbase = qkv + (size_t)b * T_ * rstride + h * HD;

    // load Q tile [128][64]
#pragma unroll
    for (int i = 0; i < 4; i++) {
        const int v = tid + i * 256;
        const int r = v >> 3;
        const int c = (v & 7) * 8;
        *(uint4*)&Qs[r][c] = *(const uint4*)(qbase + (size_t)(q0 + r) * rstride + c);
    }
    __syncthreads();

    uint32_t qf[4][4];
    const int qrow = w * 16 + (lane & 15);
#pragma unroll
    for (int kk = 0; kk < 4; kk++) {
        const int col = kk * 16 + ((lane >> 4) << 3);
        ldm_x4(qf[kk][0], qf[kk][1], qf[kk][2], qf[kk][3], smem_u32(&Qs[qrow][col]));
    }

    float of[8][4];
#pragma unroll
    for (int nf = 0; nf < 8; nf++) {
#pragma unroll
        for (int e = 0; e < 4; e++) of[nf][e] = 0.f;
    }
    float m0 = -1e30f, m1 = -1e30f, l0 = 0.f, l1 = 0.f;
    const int r_lo = lane >> 2;
    const int c_off = (lane & 3) * 2;
    const int row0 = q0 + w * 16 + r_lo;   // global q row (low); high = row0+8

    for (int k0 = 0; k0 < q0 + 128; k0 += 64) {
        // load K,V tiles [64][64]
#pragma unroll
        for (int i = 0; i < 2; i++) {
            const int v = tid + i * 256;
            const int r = v >> 3;
            const int c = (v & 7) * 8;
            const half* kp = qbase + (size_t)(k0 + r) * rstride + D_ + c;
            *(uint4*)&Ks[r][c] = *(const uint4*)(kp);
            *(uint4*)&Vs[r][c] = *(const uint4*)(kp + D_);
        }
        __syncthreads();

        // S = Q @ K^T
        float sf[8][4];
#pragma unroll
        for (int nf = 0; nf < 8; nf++) {
#pragma unroll
            for (int e = 0; e < 4; e++) sf[nf][e] = 0.f;
        }
#pragma unroll
        for (int kk = 0; kk < 4; kk++) {
            uint32_t kf[8][2];
#pragma unroll
            for (int nf4 = 0; nf4 < 4; nf4++) {
                const int row = nf4 * 16 + ((lane >> 4) << 3) + (lane & 7);
                const int col = kk * 16 + (((lane >> 3) & 1) << 3);
                uint32_t r0, r1, r2, r3;
                ldm_x4(r0, r1, r2, r3, smem_u32(&Ks[row][col]));
                kf[nf4 * 2][0] = r0;
                kf[nf4 * 2][1] = r1;
                kf[nf4 * 2 + 1][0] = r2;
                kf[nf4 * 2 + 1][1] = r3;
            }
#pragma unroll
            for (int nf = 0; nf < 8; nf++) mma16816(sf[nf], qf[kk], kf[nf]);
        }

        // scale + causal mask
        const bool domask = (k0 + 63 > row0);
#pragma unroll
        for (int nf = 0; nf < 8; nf++) {
#pragma unroll
            for (int e = 0; e < 4; e++) sf[nf][e] *= 0.125f;
            if (domask) {
                const int col = k0 + nf * 8 + c_off;
                if (col > row0) sf[nf][0] = -1e30f;
                if (col + 1 > row0) sf[nf][1] = -1e30f;
                if (col > row0 + 8) sf[nf][2] = -1e30f;
                if (col + 1 > row0 + 8) sf[nf][3] = -1e30f;
            }
        }

        // online softmax
        float mt0 = -1e30f, mt1 = -1e30f;
#pragma unroll
        for (int nf = 0; nf < 8; nf++) {
            mt0 = fmaxf(mt0, fmaxf(sf[nf][0], sf[nf][1]));
            mt1 = fmaxf(mt1, fmaxf(sf[nf][2], sf[nf][3]));
        }
        mt0 = fmaxf(mt0, __shfl_xor_sync(0xffffffffu, mt0, 1));
        mt0 = fmaxf(mt0, __shfl_xor_sync(0xffffffffu, mt0, 2));
        mt1 = fmaxf(mt1, __shfl_xor_sync(0xffffffffu, mt1, 1));
        mt1 = fmaxf(mt1, __shfl_xor_sync(0xffffffffu, mt1, 2));
        const float mn0 = fmaxf(m0, mt0);
        const float mn1 = fmaxf(m1, mt1);
        const float al0 = __expf(m0 - mn0);
        const float al1 = __expf(m1 - mn1);
        m0 = mn0;
        m1 = mn1;
        float rs0 = 0.f, rs1 = 0.f;
#pragma unroll
        for (int nf = 0; nf < 8; nf++) {
            sf[nf][0] = __expf(sf[nf][0] - mn0);
            sf[nf][1] = __expf(sf[nf][1] - mn0);
            sf[nf][2] = __expf(sf[nf][2] - mn1);
            sf[nf][3] = __expf(sf[nf][3] - mn1);
            rs0 += sf[nf][0] + sf[nf][1];
            rs1 += sf[nf][2] + sf[nf][3];
        }
        rs0 += __shfl_xor_sync(0xffffffffu, rs0, 1);
        rs0 += __shfl_xor_sync(0xffffffffu, rs0, 2);
        rs1 += __shfl_xor_sync(0xffffffffu, rs1, 1);
        rs1 += __shfl_xor_sync(0xffffffffu, rs1, 2);
        l0 = l0 * al0 + rs0;
        l1 = l1 * al1 + rs1;
#pragma unroll
        for (int nf = 0; nf < 8; nf++) {
            of[nf][0] *= al0;
            of[nf][1] *= al0;
            of[nf][2] *= al1;
            of[nf][3] *= al1;
        }

        // P fragments (A-operand layout)
        uint32_t pf[4][4];
#pragma unroll
        for (int kk = 0; kk < 4; kk++) {
            pf[kk][0] = h2u(sf[2 * kk][0], sf[2 * kk][1]);
            pf[kk][1] = h2u(sf[2 * kk][2], sf[2 * kk][3]);
            pf[kk][2] = h2u(sf[2 * kk + 1][0], sf[2 * kk + 1][1]);
            pf[kk][3] = h2u(sf[2 * kk + 1][2], sf[2 * kk + 1][3]);
        }

        // O += P @ V
#pragma unroll
        for (int kk = 0; kk < 4; kk++) {
            uint32_t vf[8][2];
#pragma unroll
            for (int nf4 = 0; nf4 < 4; nf4++) {
                const int row = kk * 16 + (lane & 15);
                const int col = nf4 * 16 + ((lane >> 4) << 3);
                uint32_t r0, r1, r2, r3;
                ldm_x4_t(r0, r1, r2, r3, smem_u32(&Vs[row][col]));
                vf[nf4 * 2][0] = r0;
                vf[nf4 * 2][1] = r1;
                vf[nf4 * 2 + 1][0] = r2;
                vf[nf4 * 2 + 1][1] = r3;
            }
#pragma unroll
            for (int nf = 0; nf < 8; nf++) mma16816(of[nf], pf[kk], vf[nf]);
        }
        __syncthreads();
    }

    const float inv0 = 1.f / l0;
    const float inv1 = 1.f / l1;
    half* obase = attno + h * HD;
#pragma unroll
    for (int nf = 0; nf < 8; nf++) {
        const int c = nf * 8 + c_off;
        *(half2*)(obase + ((size_t)b * T_ + row0) * D_ + c) =
            __floats2half2_rn(of[nf][0] * inv0, of[nf][1] * inv0);
        *(half2*)(obase + ((size_t)b * T_ + row0 + 8) * D_ + c) =
            __floats2half2_rn(of[nf][2] * inv1, of[nf][3] * inv1);
    }
}

// ---------------- rotation passes + silu + final combine ----------------
__global__ __launch_bounds__(256)
void rot_kernel(const float* __restrict__ h2, const float* __restrict__ x2,
                const float* __restrict__ angles, const float* __restrict__ gate,
                const float* __restrict__ bias, const int* __restrict__ pi,
                const int* __restrict__ pj, float* __restrict__ out) {
    const int row = blockIdx.x;
    const int tid = threadIdx.x;
    __shared__ float r[D_];
    const float* hrow = h2 + (size_t)row * D_;
#pragma unroll
    for (int i = 0; i < 4; i++) r[tid + i * 256] = hrow[tid + i * 256];
    __syncthreads();
#pragma unroll
    for (int p = 0; p < NPASS_; p++) {
        const int ii = pi[p * P_ + tid];
        const int jj = pj[p * P_ + tid];
        float sa, ca;
        sincosf(angles[p * P_ + tid], &sa, &ca);
        const float hi = r[ii];
        const float hj = r[jj];
        r[ii] = hi * ca - hj * sa;     // pi/pj disjoint within a pass
        r[jj] = hi * sa + hj * ca;
        __syncthreads();
#pragma unroll
        for (int i = 0; i < 4; i++) {
            const int d = tid + i * 256;
            const float z = r[d] * gate[p * D_ + d] + bias[p * D_ + d];
            r[d] = z / (1.f + __expf(-z));
        }
        __syncthreads();
    }
    const float* xrow = x2 + (size_t)row * D_;
    float* orow = out + (size_t)row * D_;
#pragma unroll
    for (int i = 0; i < 4; i++) {
        const int d = tid + i * 256;
        orow[d] = xrow[d] + r[d] - hrow[d];
    }
}

// ---------------- launch ----------------
extern "C" void kernel_launch(void* const* d_in, const int* in_sizes, int n_in,
                              void* d_out, int out_size) {
    const float* x      = (const float*)d_in[0];
    const float* gamma  = (const float*)d_in[1];
    const float* beta   = (const float*)d_in[2];
    const float* qkv_w  = (const float*)d_in[3];
    const float* o_w    = (const float*)d_in[4];
    const float* n1w    = (const float*)d_in[5];
    const float* n2w    = (const float*)d_in[6];
    const float* angles = (const float*)d_in[7];
    const float* gate   = (const float*)d_in[8];
    const float* bias   = (const float*)d_in[9];
    const int*   pi     = (const int*)d_in[10];
    const int*   pj     = (const int*)d_in[11];
    float* out = (float*)d_out;

    void *ph16, *pw16, *pqkv16, *patt16, *px2, *ph2;
    cudaGetSymbolAddress(&ph16, g_h16);
    cudaGetSymbolAddress(&pw16, g_w16);
    cudaGetSymbolAddress(&pqkv16, g_qkv16);
    cudaGetSymbolAddress(&patt16, g_att16);
    cudaGetSymbolAddress(&px2, g_x2);
    cudaGetSymbolAddress(&ph2, g_h2);
    half* h16   = (half*)ph16;
    half* w16   = (half*)pw16;       // [0, 3DD): qkv_w ; [3DD, 4DD): o_w
    half* qkv16 = (half*)pqkv16;
    half* att16 = (half*)patt16;
    float* x2   = (float*)px2;
    float* h2   = (float*)ph2;

    // weight conversion
    f2h4_kernel<<<(3 * D_ * D_ / 4 + 255) / 256, 256>>>(qkv_w, w16, 3 * D_ * D_ / 4);
    f2h4_kernel<<<(D_ * D_ / 4 + 255) / 256, 256>>>(o_w, w16 + 3 * D_ * D_, D_ * D_ / 4);

    // 1. h = rmsnorm(x, norm1_w) * gamma + beta  (fp16 out)
    rmsnorm_kernel<half><<<BT, 256>>>(x, n1w, gamma, beta, h16);

    // 2. qkv = h @ qkv_w^T  [4096 x 3072] fp16
    gemm16_kernel<true, false><<<dim3(3 * D_ / 128, BT / 128), 128>>>(
        h16, w16, nullptr, qkv16, BT, 3 * D_, D_);

    // 3. causal flash attention (fp16 tensor cores)
    attn16_kernel<<<dim3(T_ / 128, B_ * H_), 256>>>(qkv16, att16);

    // 4. x2 = x + attn @ o_w^T  [4096 x 1024] fp32
    gemm16_kernel<false, true><<<dim3(D_ / 128, BT / 128), 128>>>(
        att16, w16 + 3 * D_ * D_, x, x2, BT, D_, D_);

    // 5. h2 = rmsnorm(x2, norm2_w) * gamma + beta (fp32)
    rmsnorm_kernel<float><<<BT, 256>>>(x2, n2w, gamma, beta, h2);

    // 6. rotation passes + silu; out = x2 + r - h2
    rot_kernel<<<BT, 256>>>(h2, x2, angles, gate, bias, pi, pj, out);
}